// round 1
// baseline (speedup 1.0000x reference)
#include <cuda_runtime.h>
#include <math.h>

#define B_ 64
#define N_ 1024
#define C_ 256
#define K_ 512
#define T_ 64
#define NP_ 128   // T*2 (anchor,pos) / (anchor,neg) pairs

// ---------------- static device scratch (allocation-free rule) ----------------
static __device__ int   g_top_idx[B_][K_];
static __device__ int   g_neff[B_];
static __device__ float g_cent[B_][K_][3];          // transformed, gathered centroids
static __device__ float g_feat[B_][K_][C_];         // 33.5 MB
static __device__ float g_fn2[B_][K_];              // |feat|^2
static __device__ float g_fn [B_][K_];              // |feat|
static __device__ float g_G  [NP_][K_][K_];         // 134 MB: G, then reused as A
static __device__ float g_s  [NP_][K_];             // relu(cos)
static __device__ float g_qc [NP_][K_][3];          // matched centroids

// ---------------- kernel 1: masked top-K via bitonic sort ----------------
// Comparator = (value desc, index asc) exactly reproduces jax.lax.top_k's
// stable ordering, including the -1e9 padding ties (index-ascending).
__global__ void k_topk(const float* __restrict__ attn,
                       const int*   __restrict__ num_rt,
                       const float* __restrict__ cents,
                       const float* __restrict__ sas) {
    int b = blockIdx.x;
    __shared__ float sv[N_];
    __shared__ int   si[N_];
    int nr = num_rt[b];
    for (int i = threadIdx.x; i < N_; i += blockDim.x) {
        sv[i] = (i < nr) ? attn[b * N_ + i] : -1e9f;
        si[i] = i;
    }
    for (int size = 2; size <= N_; size <<= 1) {
        for (int stride = size >> 1; stride > 0; stride >>= 1) {
            __syncthreads();
            for (int i = threadIdx.x; i < N_; i += blockDim.x) {
                int j = i ^ stride;
                if (j > i) {
                    float vi = sv[i], vj = sv[j];
                    int   ii = si[i], ij = si[j];
                    bool up = ((i & size) == 0);
                    bool jFirst = (vj > vi) || (vj == vi && ij < ii);
                    bool iFirst = (vi > vj) || (vi == vj && ii < ij);
                    bool sw = up ? jFirst : iFirst;
                    if (sw) { sv[i] = vj; sv[j] = vi; si[i] = ij; si[j] = ii; }
                }
            }
        }
    }
    __syncthreads();
    float sh0 = sas[b*4+0], sh1 = sas[b*4+1], sh2 = sas[b*4+2], sc = sas[b*4+3];
    for (int k = threadIdx.x; k < K_; k += blockDim.x) {
        int id = si[k];
        g_top_idx[b][k] = id;
        const float* cp = cents + ((size_t)b * N_ + id) * 3;
        float x = cp[0], y = cp[1], z = cp[2];
        if (id < nr) { x = fmaf(x, sc, sh0); y = fmaf(y, sc, sh1); z = fmaf(z, sc, sh2); }
        g_cent[b][k][0] = x; g_cent[b][k][1] = y; g_cent[b][k][2] = z;
    }
    if (threadIdx.x == 0) g_neff[b] = nr < K_ ? nr : K_;
}

// ---------------- kernel 2: feat = gather(rt) @ W_in + b_in ----------------
// 64x64 tile, 256 threads, 4x4 microtile, fp32.
__global__ void k_feat(const float* __restrict__ rt,
                       const float* __restrict__ W_in,
                       const float* __restrict__ b_in) {
    int b    = blockIdx.z;
    int row0 = blockIdx.y * 64;
    int col0 = blockIdx.x * 64;
    __shared__ float As[16][64];
    __shared__ float Bs[16][64];
    __shared__ int rows[64];
    int tid = threadIdx.x;
    if (tid < 64) rows[tid] = g_top_idx[b][row0 + tid];
    __syncthreads();
    int tx = tid & 15, ty = tid >> 4;
    int lr = tid >> 2, lq = tid & 3;
    int bc = tid >> 4, bq = tid & 15;
    const float* rtb = rt + (size_t)b * N_ * C_;
    int arow = rows[lr];
    float acc[4][4];
#pragma unroll
    for (int i = 0; i < 4; i++)
#pragma unroll
        for (int j = 0; j < 4; j++) acc[i][j] = 0.f;

    for (int kk = 0; kk < C_; kk += 16) {
        float4 av = *(const float4*)(rtb + (size_t)arow * C_ + kk + lq * 4);
        As[lq*4+0][lr] = av.x; As[lq*4+1][lr] = av.y;
        As[lq*4+2][lr] = av.z; As[lq*4+3][lr] = av.w;
        float4 bv = *(const float4*)(W_in + (size_t)(kk + bc) * C_ + col0 + bq * 4);
        *(float4*)&Bs[bc][bq*4] = bv;
        __syncthreads();
#pragma unroll
        for (int c = 0; c < 16; c++) {
            float a[4], w[4];
            *(float4*)a = *(const float4*)&As[c][ty*4];
            *(float4*)w = *(const float4*)&Bs[c][tx*4];
#pragma unroll
            for (int i = 0; i < 4; i++)
#pragma unroll
                for (int j = 0; j < 4; j++)
                    acc[i][j] = fmaf(a[i], w[j], acc[i][j]);
        }
        __syncthreads();
    }
#pragma unroll
    for (int i = 0; i < 4; i++) {
        int row = row0 + ty*4 + i;
        float4 o;
        o.x = acc[i][0] + b_in[col0 + tx*4 + 0];
        o.y = acc[i][1] + b_in[col0 + tx*4 + 1];
        o.z = acc[i][2] + b_in[col0 + tx*4 + 2];
        o.w = acc[i][3] + b_in[col0 + tx*4 + 3];
        *(float4*)&g_feat[b][row][col0 + tx*4] = o;
    }
}

// ---------------- kernel 2b: per-row feature norms ----------------
__global__ void k_norm() {
    int row  = blockIdx.x * 8 + (threadIdx.x >> 5);
    int lane = threadIdx.x & 31;
    const float* f = &g_feat[0][0][0] + (size_t)row * C_;
    float4 u = *(const float4*)(f + lane * 8);
    float4 w = *(const float4*)(f + lane * 8 + 4);
    float s = u.x*u.x + u.y*u.y + u.z*u.z + u.w*u.w
            + w.x*w.x + w.y*w.y + w.z*w.z + w.w*w.w;
#pragma unroll
    for (int o = 16; o; o >>= 1) s += __shfl_xor_sync(0xffffffffu, s, o);
    if (lane == 0) {
        ((float*)g_fn2)[row] = s;
        ((float*)g_fn )[row] = sqrtf(s);
    }
}

// ---------------- kernel 3: G[p] = feat[anc] @ feat[nb]^T (NT GEMM) ----------------
__global__ void k_gemmG(const int* __restrict__ anc,
                        const int* __restrict__ pos,
                        const int* __restrict__ neg) {
    int p = blockIdx.z;
    int t = p >> 1, n = p & 1;
    int ba = anc[t];
    int bb = n ? neg[t] : pos[t];
    int row0 = blockIdx.y * 64;
    int col0 = blockIdx.x * 64;
    __shared__ float As[16][64];
    __shared__ float Bs[16][64];
    int tid = threadIdx.x;
    int tx = tid & 15, ty = tid >> 4;
    int lr = tid >> 2, lq = tid & 3;
    const float* fa = &g_feat[ba][0][0];
    const float* fb = &g_feat[bb][0][0];
    float acc[4][4];
#pragma unroll
    for (int i = 0; i < 4; i++)
#pragma unroll
        for (int j = 0; j < 4; j++) acc[i][j] = 0.f;

    for (int kk = 0; kk < C_; kk += 16) {
        float4 av = *(const float4*)(fa + (size_t)(row0 + lr) * C_ + kk + lq * 4);
        As[lq*4+0][lr] = av.x; As[lq*4+1][lr] = av.y;
        As[lq*4+2][lr] = av.z; As[lq*4+3][lr] = av.w;
        float4 bv = *(const float4*)(fb + (size_t)(col0 + lr) * C_ + kk + lq * 4);
        Bs[lq*4+0][lr] = bv.x; Bs[lq*4+1][lr] = bv.y;
        Bs[lq*4+2][lr] = bv.z; Bs[lq*4+3][lr] = bv.w;
        __syncthreads();
#pragma unroll
        for (int c = 0; c < 16; c++) {
            float a[4], w[4];
            *(float4*)a = *(const float4*)&As[c][ty*4];
            *(float4*)w = *(const float4*)&Bs[c][tx*4];
#pragma unroll
            for (int i = 0; i < 4; i++)
#pragma unroll
                for (int j = 0; j < 4; j++)
                    acc[i][j] = fmaf(a[i], w[j], acc[i][j]);
        }
        __syncthreads();
    }
#pragma unroll
    for (int i = 0; i < 4; i++) {
        float4 o; o.x = acc[i][0]; o.y = acc[i][1]; o.z = acc[i][2]; o.w = acc[i][3];
        *(float4*)&g_G[p][row0 + ty*4 + i][col0 + tx*4] = o;
    }
}

// ---------------- kernel 4: corr = argmin_l fd, cos, s, q_c ----------------
// fd[k,l] = |a_k|^2 + |b_l|^2 - 2 G[k,l]; the |a_k|^2 term is row-constant.
// Unmasked argmin with first-index tie-break (== jnp.argmin).
__global__ void k_corr(const int* __restrict__ anc,
                       const int* __restrict__ pos,
                       const int* __restrict__ neg) {
    int p = blockIdx.x;
    int t = p >> 1, n = p & 1;
    int ba = anc[t];
    int bb = n ? neg[t] : pos[t];
    int warp = threadIdx.x >> 5, lane = threadIdx.x & 31;
    for (int k = warp; k < K_; k += 16) {
        const float* Grow = &g_G[p][k][0];
        float best = 3.4e38f; int bidx = K_;
        for (int l = lane; l < K_; l += 32) {
            float v = g_fn2[bb][l] - 2.f * Grow[l];
            if (v < best) { best = v; bidx = l; }   // l increasing => first-index kept
        }
#pragma unroll
        for (int o = 16; o; o >>= 1) {
            float ov = __shfl_xor_sync(0xffffffffu, best, o);
            int   oi = __shfl_xor_sync(0xffffffffu, bidx, o);
            if (ov < best || (ov == best && oi < bidx)) { best = ov; bidx = oi; }
        }
        if (lane == 0) {
            float dot  = Grow[bidx];
            float cosv = dot / (g_fn[ba][k] * g_fn[bb][bidx] + 1e-8f);
            g_s[p][k] = cosv > 0.f ? cosv : 0.f;
            g_qc[p][k][0] = g_cent[bb][bidx][0];
            g_qc[p][k][1] = g_cent[bb][bidx][1];
            g_qc[p][k][2] = g_cent[bb][bidx][2];
        }
    }
}

// ---------------- kernel 5: build A in place over g_G ----------------
// geo test |sqrt(a)-sqrt(b)| < 0.5 rewritten sqrt-free:
//   u = a + b - 0.25;  geo <=> (u < 0) || (4ab > u^2)     (exact algebra)
__global__ void k_buildA(const int* __restrict__ anc,
                         const int* __restrict__ pos,
                         const int* __restrict__ neg) {
    int p  = blockIdx.y;
    int r0 = blockIdx.x * 64;
    int t = p >> 1, n = p & 1;
    int ba = anc[t];
    int bb = n ? neg[t] : pos[t];
    __shared__ float px[K_], py[K_], pz[K_], pn[K_];
    __shared__ float qx[K_], qy[K_], qz[K_], qn[K_];
    __shared__ float ss[K_];
    int tid = threadIdx.x;
    for (int i = tid; i < K_; i += blockDim.x) {
        float x = g_cent[ba][i][0], y = g_cent[ba][i][1], z = g_cent[ba][i][2];
        px[i] = x; py[i] = y; pz[i] = z; pn[i] = x*x + y*y + z*z;
        x = g_qc[p][i][0]; y = g_qc[p][i][1]; z = g_qc[p][i][2];
        qx[i] = x; qy[i] = y; qz[i] = z; qn[i] = x*x + y*y + z*z;
        ss[i] = g_s[p][i];
    }
    __syncthreads();
    int neffa = g_neff[ba], neffb = g_neff[bb];
    for (int e = tid; e < 64 * K_; e += blockDim.x) {
        int k = r0 + (e >> 9);
        int l = e & (K_ - 1);
        float dp2 = fmaxf(pn[k] + pn[l] - 2.f*(px[k]*px[l] + py[k]*py[l] + pz[k]*pz[l]), 0.f) + 1e-12f;
        float dq2 = fmaxf(qn[k] + qn[l] - 2.f*(qx[k]*qx[l] + qy[k]*qy[l] + qz[k]*qz[l]), 0.f) + 1e-12f;
        float u = dp2 + dq2 - 0.25f;
        bool geo = (u < 0.f) || (4.f * dp2 * dq2 > u * u);
        bool ok = geo && (k < neffa) && (l < neffb) && (k != l);
        g_G[p][k][l] = ok ? ss[k] * ss[l] : 0.f;
    }
}

// ---------------- kernel 6: power iteration + sort + MLP + output ----------------
__global__ void k_power(const float* __restrict__ W1, const float* __restrict__ b1,
                        const float* __restrict__ W2, const float* __restrict__ b2,
                        float* __restrict__ out) {
    int p = blockIdx.x;
    int tid = threadIdx.x;
    int warp = tid >> 5, lane = tid & 31;
    __shared__ float v[K_];
    __shared__ float w[K_];
    __shared__ float red[16];
    v[tid] = 0.044194173824159216f;   // 1/sqrt(512)
    __syncthreads();
    for (int it = 0; it < 20; it++) {
        for (int k = warp; k < K_; k += 16) {
            const float* Arow = &g_G[p][k][0];
            float acc = 0.f;
#pragma unroll 4
            for (int l = lane; l < K_; l += 32)
                acc = fmaf(Arow[l], v[l], acc);
#pragma unroll
            for (int o = 16; o; o >>= 1) acc += __shfl_xor_sync(0xffffffffu, acc, o);
            if (lane == 0) w[k] = acc;
        }
        __syncthreads();
        float x = w[tid];
        float sq = x * x;
#pragma unroll
        for (int o = 16; o; o >>= 1) sq += __shfl_xor_sync(0xffffffffu, sq, o);
        if (lane == 0) red[warp] = sq;
        __syncthreads();
        if (warp == 0) {
            float r = (lane < 16) ? red[lane] : 0.f;
#pragma unroll
            for (int o = 8; o; o >>= 1) r += __shfl_xor_sync(0xffffffffu, r, o);
            if (lane == 0) red[0] = 1.f / (sqrtf(r) + 1e-8f);
        }
        __syncthreads();
        v[tid] = x * red[0];
        __syncthreads();
    }
    // bitonic sort v descending -> eig
    for (int size = 2; size <= K_; size <<= 1) {
        for (int stride = size >> 1; stride > 0; stride >>= 1) {
            int i = tid, j = i ^ stride;
            if (j > i) {
                float vi = v[i], vj = v[j];
                bool up = ((i & size) == 0);
                bool sw = up ? (vj > vi) : (vi > vj);
                if (sw) { v[i] = vj; v[j] = vi; }
            }
            __syncthreads();
        }
    }
    // h = relu(eig @ W1 + b1); score = sigmoid(h @ W2 + b2)
    float hj = b1[tid];
#pragma unroll 4
    for (int k = 0; k < K_; k++)
        hj = fmaf(v[k], W1[(size_t)k * K_ + tid], hj);
    hj = hj > 0.f ? hj : 0.f;
    float contrib = hj * W2[tid];
#pragma unroll
    for (int o = 16; o; o >>= 1) contrib += __shfl_xor_sync(0xffffffffu, contrib, o);
    if (lane == 0) red[warp] = contrib;
    __syncthreads();
    if (tid == 0) {
        float sum = 0.f;
#pragma unroll
        for (int i = 0; i < 16; i++) sum += red[i];
        sum += b2[0];
        out[p]       = 1.f / (1.f + expf(-sum));       // scores (T,2,1) flattened
        out[NP_ + p] = (p & 1) ? 0.f : 1.f;            // targets: [:,0]=1
    }
}

extern "C" void kernel_launch(void* const* d_in, const int* in_sizes, int n_in,
                              void* d_out, int out_size) {
    const float* rt     = (const float*)d_in[0];
    const float* cents  = (const float*)d_in[1];
    const float* attn   = (const float*)d_in[2];
    const float* sas    = (const float*)d_in[3];
    const int*   num_rt = (const int*)  d_in[4];
    const int*   anc    = (const int*)  d_in[5];
    const int*   pos    = (const int*)  d_in[6];
    const int*   neg    = (const int*)  d_in[7];
    const float* W_in   = (const float*)d_in[8];
    const float* b_in   = (const float*)d_in[9];
    const float* W1     = (const float*)d_in[10];
    const float* b1     = (const float*)d_in[11];
    const float* W2     = (const float*)d_in[12];
    const float* b2     = (const float*)d_in[13];
    float* out = (float*)d_out;

    k_topk <<<B_, 512>>>(attn, num_rt, cents, sas);
    k_feat <<<dim3(C_/64, K_/64, B_), 256>>>(rt, W_in, b_in);
    k_norm <<<B_*K_/8, 256>>>();
    k_gemmG<<<dim3(K_/64, K_/64, NP_), 256>>>(anc, pos, neg);
    k_corr <<<NP_, 512>>>(anc, pos, neg);
    k_buildA<<<dim3(K_/64, NP_), 256>>>(anc, pos, neg);
    k_power<<<NP_, 512>>>(W1, b1, W2, b2, out);
}

// round 2
// speedup vs baseline: 2.5326x; 2.5326x over previous
#include <cuda_runtime.h>
#include <math.h>

#define B_ 64
#define N_ 1024
#define C_ 256
#define K_ 512
#define T_ 64
#define NP_ 128   // T*2 (anchor,pos)/(anchor,neg) pairs

// ---------------- static device scratch (allocation-free rule) ----------------
static __device__ int      g_top_idx[B_][K_];
static __device__ int      g_neff[B_];
static __device__ float    g_cent[B_][K_][3];
static __device__ float    g_feat[B_][K_][C_];        // 33.5 MB
static __device__ float    g_fn2[B_][K_];
static __device__ float    g_fn [B_][K_];
static __device__ float    g_G  [NP_][K_][K_];        // 134 MB: Gram matrix (read by k_corr)
static __device__ float    g_s  [NP_][K_];            // relu(cos)
static __device__ float    g_qc [NP_][K_][3];         // matched centroids
static __device__ unsigned g_mask[NP_][K_][16];       // 4 MB: geo&valid bitmask

// ---------------- kernel 1: masked top-K via bitonic sort ----------------
__global__ void k_topk(const float* __restrict__ attn,
                       const int*   __restrict__ num_rt,
                       const float* __restrict__ cents,
                       const float* __restrict__ sas) {
    int b = blockIdx.x;
    __shared__ float sv[N_];
    __shared__ int   si[N_];
    int nr = num_rt[b];
    for (int i = threadIdx.x; i < N_; i += blockDim.x) {
        sv[i] = (i < nr) ? attn[b * N_ + i] : -1e9f;
        si[i] = i;
    }
    for (int size = 2; size <= N_; size <<= 1) {
        for (int stride = size >> 1; stride > 0; stride >>= 1) {
            __syncthreads();
            for (int i = threadIdx.x; i < N_; i += blockDim.x) {
                int j = i ^ stride;
                if (j > i) {
                    float vi = sv[i], vj = sv[j];
                    int   ii = si[i], ij = si[j];
                    bool up = ((i & size) == 0);
                    bool jFirst = (vj > vi) || (vj == vi && ij < ii);
                    bool iFirst = (vi > vj) || (vi == vj && ii < ij);
                    bool sw = up ? jFirst : iFirst;
                    if (sw) { sv[i] = vj; sv[j] = vi; si[i] = ij; si[j] = ii; }
                }
            }
        }
    }
    __syncthreads();
    float sh0 = sas[b*4+0], sh1 = sas[b*4+1], sh2 = sas[b*4+2], sc = sas[b*4+3];
    for (int k = threadIdx.x; k < K_; k += blockDim.x) {
        int id = si[k];
        g_top_idx[b][k] = id;
        const float* cp = cents + ((size_t)b * N_ + id) * 3;
        float x = cp[0], y = cp[1], z = cp[2];
        if (id < nr) { x = fmaf(x, sc, sh0); y = fmaf(y, sc, sh1); z = fmaf(z, sc, sh2); }
        g_cent[b][k][0] = x; g_cent[b][k][1] = y; g_cent[b][k][2] = z;
    }
    if (threadIdx.x == 0) g_neff[b] = nr < K_ ? nr : K_;
}

// ---------------- kernel 2: feat = gather(rt) @ W_in + b_in ----------------
// 128x128 tile, 256 threads, 8x8 microtile (split 4+4 fragments), reg prefetch.
__global__ void __launch_bounds__(256, 2)
k_feat(const float* __restrict__ rt,
       const float* __restrict__ W_in,
       const float* __restrict__ b_in) {
    int b    = blockIdx.z;
    int row0 = blockIdx.y * 128;
    int col0 = blockIdx.x * 128;
    __shared__ float As[16][128];
    __shared__ float Bs[16][128];
    __shared__ int rows[128];
    int tid = threadIdx.x;
    if (tid < 128) rows[tid] = g_top_idx[b][row0 + tid];
    __syncthreads();
    int tx = tid & 15, ty = tid >> 4;
    int lr = tid >> 1, lq = (tid & 1) * 2;   // A loader: row lr, k-quads lq,lq+1
    int wc = tid >> 4, wq = tid & 15;        // B loader: k-row wc, col quad wq
    const float* rtb = rt + (size_t)b * N_ * C_;
    size_t arow = (size_t)rows[lr];
    float acc[8][8];
#pragma unroll
    for (int i = 0; i < 8; i++)
#pragma unroll
        for (int j = 0; j < 8; j++) acc[i][j] = 0.f;

    float4 ra[2], rb[2];
#pragma unroll
    for (int i = 0; i < 2; i++) {
        ra[i] = *(const float4*)(rtb + arow * C_ + (lq + i) * 4);
        rb[i] = *(const float4*)(W_in + (size_t)wc * C_ + col0 + i * 64 + wq * 4);
    }
    for (int kk = 0; kk < C_; kk += 16) {
        __syncthreads();
#pragma unroll
        for (int i = 0; i < 2; i++) {
            int q = lq + i;
            As[q*4+0][lr] = ra[i].x; As[q*4+1][lr] = ra[i].y;
            As[q*4+2][lr] = ra[i].z; As[q*4+3][lr] = ra[i].w;
            *(float4*)&Bs[wc][i * 64 + wq * 4] = rb[i];
        }
        __syncthreads();
        if (kk + 16 < C_) {
#pragma unroll
            for (int i = 0; i < 2; i++) {
                ra[i] = *(const float4*)(rtb + arow * C_ + kk + 16 + (lq + i) * 4);
                rb[i] = *(const float4*)(W_in + (size_t)(kk + 16 + wc) * C_ + col0 + i * 64 + wq * 4);
            }
        }
#pragma unroll
        for (int c = 0; c < 16; c++) {
            float a[8], w[8];
            *(float4*)&a[0] = *(const float4*)&As[c][ty * 4];
            *(float4*)&a[4] = *(const float4*)&As[c][64 + ty * 4];
            *(float4*)&w[0] = *(const float4*)&Bs[c][tx * 4];
            *(float4*)&w[4] = *(const float4*)&Bs[c][64 + tx * 4];
#pragma unroll
            for (int i = 0; i < 8; i++)
#pragma unroll
                for (int j = 0; j < 8; j++)
                    acc[i][j] = fmaf(a[i], w[j], acc[i][j]);
        }
    }
    float bias[8];
#pragma unroll
    for (int j = 0; j < 8; j++)
        bias[j] = b_in[col0 + (j < 4 ? tx * 4 + j : 64 + tx * 4 + j - 4)];
#pragma unroll
    for (int i = 0; i < 8; i++) {
        int row = row0 + (i < 4 ? ty * 4 + i : 64 + ty * 4 + i - 4);
        float4 o0, o1;
        o0.x = acc[i][0] + bias[0]; o0.y = acc[i][1] + bias[1];
        o0.z = acc[i][2] + bias[2]; o0.w = acc[i][3] + bias[3];
        o1.x = acc[i][4] + bias[4]; o1.y = acc[i][5] + bias[5];
        o1.z = acc[i][6] + bias[6]; o1.w = acc[i][7] + bias[7];
        *(float4*)&g_feat[b][row][col0 + tx * 4]      = o0;
        *(float4*)&g_feat[b][row][col0 + 64 + tx * 4] = o1;
    }
}

// ---------------- kernel 2b: per-row feature norms ----------------
__global__ void k_norm() {
    int row  = blockIdx.x * 8 + (threadIdx.x >> 5);
    int lane = threadIdx.x & 31;
    const float* f = &g_feat[0][0][0] + (size_t)row * C_;
    float4 u = *(const float4*)(f + lane * 8);
    float4 w = *(const float4*)(f + lane * 8 + 4);
    float s = u.x*u.x + u.y*u.y + u.z*u.z + u.w*u.w
            + w.x*w.x + w.y*w.y + w.z*w.z + w.w*w.w;
#pragma unroll
    for (int o = 16; o; o >>= 1) s += __shfl_xor_sync(0xffffffffu, s, o);
    if (lane == 0) {
        ((float*)g_fn2)[row] = s;
        ((float*)g_fn )[row] = sqrtf(s);
    }
}

// ---------------- kernel 3: G[p] = feat[anc] @ feat[nb]^T (NT GEMM) ----------------
// 128x128 tile, 256 threads, 8x8 microtile, reg prefetch.
__global__ void __launch_bounds__(256, 2)
k_gemmG(const int* __restrict__ anc,
        const int* __restrict__ pos,
        const int* __restrict__ neg) {
    int p = blockIdx.z;
    int t = p >> 1, n = p & 1;
    int ba = anc[t];
    int bb = n ? neg[t] : pos[t];
    int row0 = blockIdx.y * 128;
    int col0 = blockIdx.x * 128;
    __shared__ float As[16][128];
    __shared__ float Bs[16][128];
    int tid = threadIdx.x;
    int tx = tid & 15, ty = tid >> 4;
    int lr = tid >> 1, lq = (tid & 1) * 2;
    const float* fa = &g_feat[ba][row0][0];
    const float* fb = &g_feat[bb][col0][0];
    float acc[8][8];
#pragma unroll
    for (int i = 0; i < 8; i++)
#pragma unroll
        for (int j = 0; j < 8; j++) acc[i][j] = 0.f;

    float4 ra[2], rb[2];
#pragma unroll
    for (int i = 0; i < 2; i++) {
        ra[i] = *(const float4*)(fa + (size_t)lr * C_ + (lq + i) * 4);
        rb[i] = *(const float4*)(fb + (size_t)lr * C_ + (lq + i) * 4);
    }
    for (int kk = 0; kk < C_; kk += 16) {
        __syncthreads();
#pragma unroll
        for (int i = 0; i < 2; i++) {
            int q = lq + i;
            As[q*4+0][lr] = ra[i].x; As[q*4+1][lr] = ra[i].y;
            As[q*4+2][lr] = ra[i].z; As[q*4+3][lr] = ra[i].w;
            Bs[q*4+0][lr] = rb[i].x; Bs[q*4+1][lr] = rb[i].y;
            Bs[q*4+2][lr] = rb[i].z; Bs[q*4+3][lr] = rb[i].w;
        }
        __syncthreads();
        if (kk + 16 < C_) {
#pragma unroll
            for (int i = 0; i < 2; i++) {
                ra[i] = *(const float4*)(fa + (size_t)lr * C_ + kk + 16 + (lq + i) * 4);
                rb[i] = *(const float4*)(fb + (size_t)lr * C_ + kk + 16 + (lq + i) * 4);
            }
        }
#pragma unroll
        for (int c = 0; c < 16; c++) {
            float a[8], w[8];
            *(float4*)&a[0] = *(const float4*)&As[c][ty * 4];
            *(float4*)&a[4] = *(const float4*)&As[c][64 + ty * 4];
            *(float4*)&w[0] = *(const float4*)&Bs[c][tx * 4];
            *(float4*)&w[4] = *(const float4*)&Bs[c][64 + tx * 4];
#pragma unroll
            for (int i = 0; i < 8; i++)
#pragma unroll
                for (int j = 0; j < 8; j++)
                    acc[i][j] = fmaf(a[i], w[j], acc[i][j]);
        }
    }
#pragma unroll
    for (int i = 0; i < 8; i++) {
        int row = row0 + (i < 4 ? ty * 4 + i : 64 + ty * 4 + i - 4);
        float4 o0, o1;
        o0.x = acc[i][0]; o0.y = acc[i][1]; o0.z = acc[i][2]; o0.w = acc[i][3];
        o1.x = acc[i][4]; o1.y = acc[i][5]; o1.z = acc[i][6]; o1.w = acc[i][7];
        *(float4*)&g_G[p][row][col0 + tx * 4]      = o0;
        *(float4*)&g_G[p][row][col0 + 64 + tx * 4] = o1;
    }
}

// ---------------- kernel 4: corr = argmin_l fd, cos, s, q_c ----------------
__global__ void k_corr(const int* __restrict__ anc,
                       const int* __restrict__ pos,
                       const int* __restrict__ neg) {
    int p = blockIdx.x;
    int t = p >> 1, n = p & 1;
    int ba = anc[t];
    int bb = n ? neg[t] : pos[t];
    int warp = threadIdx.x >> 5, lane = threadIdx.x & 31;
    for (int k = warp; k < K_; k += 16) {
        const float* Grow = &g_G[p][k][0];
        float best = 3.4e38f; int bidx = K_;
        for (int l = lane; l < K_; l += 32) {
            float v = g_fn2[bb][l] - 2.f * Grow[l];
            if (v < best) { best = v; bidx = l; }
        }
#pragma unroll
        for (int o = 16; o; o >>= 1) {
            float ov = __shfl_xor_sync(0xffffffffu, best, o);
            int   oi = __shfl_xor_sync(0xffffffffu, bidx, o);
            if (ov < best || (ov == best && oi < bidx)) { best = ov; bidx = oi; }
        }
        if (lane == 0) {
            float dot  = Grow[bidx];
            float cosv = dot / (g_fn[ba][k] * g_fn[bb][bidx] + 1e-8f);
            g_s[p][k] = cosv > 0.f ? cosv : 0.f;
            g_qc[p][k][0] = g_cent[bb][bidx][0];
            g_qc[p][k][1] = g_cent[bb][bidx][1];
            g_qc[p][k][2] = g_cent[bb][bidx][2];
        }
    }
}

// ---------------- kernel 5: build geo bitmask (A = mask .* s s^T implied) ----------------
// geo |sqrt(a)-sqrt(b)|<0.5 rewritten sqrt-free: u=a+b-0.25; geo <=> u<0 || 4ab>u^2
__global__ void k_buildM(const int* __restrict__ anc,
                         const int* __restrict__ pos,
                         const int* __restrict__ neg) {
    int p = blockIdx.x;
    int t = p >> 1, n = p & 1;
    int ba = anc[t];
    int bb = n ? neg[t] : pos[t];
    __shared__ float px[K_], py[K_], pz[K_], pn[K_];
    __shared__ float qx[K_], qy[K_], qz[K_], qn[K_];
    int tid = threadIdx.x;
    {
        float x = g_cent[ba][tid][0], y = g_cent[ba][tid][1], z = g_cent[ba][tid][2];
        px[tid] = x; py[tid] = y; pz[tid] = z; pn[tid] = x*x + y*y + z*z;
        x = g_qc[p][tid][0]; y = g_qc[p][tid][1]; z = g_qc[p][tid][2];
        qx[tid] = x; qy[tid] = y; qz[tid] = z; qn[tid] = x*x + y*y + z*z;
    }
    __syncthreads();
    int neffa = g_neff[ba], neffb = g_neff[bb];
    int warp = tid >> 5, lane = tid & 31;
    for (int k = warp; k < K_; k += 16) {
        float pxk = px[k], pyk = py[k], pzk = pz[k], pnk = pn[k];
        float qxk = qx[k], qyk = qy[k], qzk = qz[k], qnk = qn[k];
        bool kv = (k < neffa);
#pragma unroll 4
        for (int w = 0; w < 16; w++) {
            int l = w * 32 + lane;
            float dp2 = fmaxf(pnk + pn[l] - 2.f*(pxk*px[l] + pyk*py[l] + pzk*pz[l]), 0.f) + 1e-12f;
            float dq2 = fmaxf(qnk + qn[l] - 2.f*(qxk*qx[l] + qyk*qy[l] + qzk*qz[l]), 0.f) + 1e-12f;
            float u = dp2 + dq2 - 0.25f;
            bool geo = (u < 0.f) || (4.f * dp2 * dq2 > u * u);
            bool ok = geo && kv && (l < neffb) && (l != k);
            unsigned word = __ballot_sync(0xffffffffu, ok);
            if (lane == 0) g_mask[p][k][w] = word;
        }
    }
}

// ---------------- kernel 6: masked power iteration + sort + MLP ----------------
// w_k = s_k * sum_{l: mask} (s_l * v_l); mask fully SMEM-resident (32KB).
__global__ void k_power(const float* __restrict__ W1, const float* __restrict__ b1,
                        const float* __restrict__ W2, const float* __restrict__ b2,
                        float* __restrict__ out) {
    int p = blockIdx.x;
    int tid = threadIdx.x;
    int warp = tid >> 5, lane = tid & 31;
    __shared__ unsigned msk[K_][16];           // 32 KB
    __shared__ float v[K_], w[K_], u[K_], s_sm[K_];
    __shared__ float red[16];
    {
        const uint4* gm = (const uint4*)&g_mask[p][0][0];
        uint4* sm = (uint4*)&msk[0][0];
        for (int i = tid; i < K_ * 4; i += 512) sm[i] = gm[i];
    }
    s_sm[tid] = g_s[p][tid];
    v[tid] = 0.044194173824159216f;            // 1/sqrt(512)
    __syncthreads();
    for (int it = 0; it < 20; it++) {
        u[tid] = s_sm[tid] * v[tid];
        __syncthreads();
        float ur[16];
#pragma unroll
        for (int c = 0; c < 16; c++) ur[c] = u[c * 32 + lane];
        for (int k = warp; k < K_; k += 16) {
            const uint4* m4 = (const uint4*)msk[k];
            float acc = 0.f;
#pragma unroll
            for (int c4 = 0; c4 < 4; c4++) {
                uint4 mw = m4[c4];
                if ((mw.x >> lane) & 1u) acc += ur[c4 * 4 + 0];
                if ((mw.y >> lane) & 1u) acc += ur[c4 * 4 + 1];
                if ((mw.z >> lane) & 1u) acc += ur[c4 * 4 + 2];
                if ((mw.w >> lane) & 1u) acc += ur[c4 * 4 + 3];
            }
#pragma unroll
            for (int o = 16; o; o >>= 1) acc += __shfl_xor_sync(0xffffffffu, acc, o);
            if (lane == 0) w[k] = acc * s_sm[k];
        }
        __syncthreads();
        float x = w[tid];
        float sq = x * x;
#pragma unroll
        for (int o = 16; o; o >>= 1) sq += __shfl_xor_sync(0xffffffffu, sq, o);
        if (lane == 0) red[warp] = sq;
        __syncthreads();
        if (warp == 0) {
            float r = (lane < 16) ? red[lane] : 0.f;
#pragma unroll
            for (int o = 8; o; o >>= 1) r += __shfl_xor_sync(0xffffffffu, r, o);
            if (lane == 0) red[0] = 1.f / (sqrtf(r) + 1e-8f);
        }
        __syncthreads();
        v[tid] = x * red[0];
        __syncthreads();
    }
    // bitonic sort v descending -> eig
    for (int size = 2; size <= K_; size <<= 1) {
        for (int stride = size >> 1; stride > 0; stride >>= 1) {
            int i = tid, j = i ^ stride;
            if (j > i) {
                float vi = v[i], vj = v[j];
                bool up = ((i & size) == 0);
                bool sw = up ? (vj > vi) : (vi > vj);
                if (sw) { v[i] = vj; v[j] = vi; }
            }
            __syncthreads();
        }
    }
    // h = relu(eig @ W1 + b1); score = sigmoid(h @ W2 + b2)
    float hj = b1[tid];
#pragma unroll 4
    for (int k = 0; k < K_; k++)
        hj = fmaf(v[k], W1[(size_t)k * K_ + tid], hj);
    hj = hj > 0.f ? hj : 0.f;
    float contrib = hj * W2[tid];
#pragma unroll
    for (int o = 16; o; o >>= 1) contrib += __shfl_xor_sync(0xffffffffu, contrib, o);
    if (lane == 0) red[warp] = contrib;
    __syncthreads();
    if (tid == 0) {
        float sum = 0.f;
#pragma unroll
        for (int i = 0; i < 16; i++) sum += red[i];
        sum += b2[0];
        out[p]       = 1.f / (1.f + expf(-sum));
        out[NP_ + p] = (p & 1) ? 0.f : 1.f;
    }
}

extern "C" void kernel_launch(void* const* d_in, const int* in_sizes, int n_in,
                              void* d_out, int out_size) {
    const float* rt     = (const float*)d_in[0];
    const float* cents  = (const float*)d_in[1];
    const float* attn   = (const float*)d_in[2];
    const float* sas    = (const float*)d_in[3];
    const int*   num_rt = (const int*)  d_in[4];
    const int*   anc    = (const int*)  d_in[5];
    const int*   pos    = (const int*)  d_in[6];
    const int*   neg    = (const int*)  d_in[7];
    const float* W_in   = (const float*)d_in[8];
    const float* b_in   = (const float*)d_in[9];
    const float* W1     = (const float*)d_in[10];
    const float* b1     = (const float*)d_in[11];
    const float* W2     = (const float*)d_in[12];
    const float* b2     = (const float*)d_in[13];
    float* out = (float*)d_out;

    k_topk  <<<B_, 512>>>(attn, num_rt, cents, sas);
    k_feat  <<<dim3(C_/128, K_/128, B_), 256>>>(rt, W_in, b_in);
    k_norm  <<<B_*K_/8, 256>>>();
    k_gemmG <<<dim3(K_/128, K_/128, NP_), 256>>>(anc, pos, neg);
    k_corr  <<<NP_, 512>>>(anc, pos, neg);
    k_buildM<<<NP_, 512>>>(anc, pos, neg);
    k_power <<<NP_, 512>>>(W1, b1, W2, b2, out);
}

// round 4
// speedup vs baseline: 3.9213x; 1.5483x over previous
#include <cuda_runtime.h>
#include <cuda_bf16.h>
#include <math.h>
#include <stdint.h>

#define B_ 64
#define N_ 1024
#define C_ 256
#define K_ 512
#define T_ 64
#define NP_ 128   // T*2 pairs

// ---------------- static device scratch ----------------
static __device__ int      g_top_idx[B_][K_];
static __device__ int      g_neff[B_];
static __device__ float    g_cent[B_][K_][3];
static __device__ __align__(16) __nv_bfloat16 g_fbh[B_][K_][C_];  // 16.7 MB hi
static __device__ __align__(16) __nv_bfloat16 g_fbl[B_][K_][C_];  // 16.7 MB lo
static __device__ float    g_fn2p[B_][K_][2];
static __device__ float    g_fn2[B_][K_];
static __device__ float    g_fn [B_][K_];
static __device__ float    g_pmv[NP_][K_][8];     // partial argmin values
static __device__ int      g_pmi[NP_][K_][8];     // partial argmin indices
static __device__ float    g_s  [NP_][K_];
static __device__ float    g_qc [NP_][K_][3];
static __device__ unsigned g_mask[NP_][K_][16];

// ---------------- asm helpers ----------------
__device__ __forceinline__ uint32_t smem_u32(const void* p) {
    uint32_t a;
    asm("{ .reg .u64 t; cvta.to.shared.u64 t, %1; cvt.u32.u64 %0, t; }" : "=r"(a) : "l"(p));
    return a;
}
__device__ __forceinline__ void ldsm4(uint32_t* r, uint32_t a) {
    asm volatile("ldmatrix.sync.aligned.m8n8.x4.shared.b16 {%0,%1,%2,%3}, [%4];"
        : "=r"(r[0]), "=r"(r[1]), "=r"(r[2]), "=r"(r[3]) : "r"(a));
}
__device__ __forceinline__ void mma16816(float* c, const uint32_t* a, uint32_t b0, uint32_t b1) {
    asm volatile("mma.sync.aligned.m16n8k16.row.col.f32.bf16.bf16.f32 "
        "{%0,%1,%2,%3}, {%4,%5,%6,%7}, {%8,%9}, {%0,%1,%2,%3};"
        : "+f"(c[0]), "+f"(c[1]), "+f"(c[2]), "+f"(c[3])
        : "r"(a[0]), "r"(a[1]), "r"(a[2]), "r"(a[3]), "r"(b0), "r"(b1));
}
#define CP_ASYNC16(dst, src) asm volatile("cp.async.cg.shared.global [%0], [%1], 16;" :: "r"(dst), "l"(src))
#define CP_COMMIT()          asm volatile("cp.async.commit_group;" ::: "memory")
#define CP_WAIT0()           asm volatile("cp.async.wait_group 0;" ::: "memory")

// ---------------- kernel 1: masked top-K via bitonic sort ----------------
__global__ void k_topk(const float* __restrict__ attn,
                       const int*   __restrict__ num_rt,
                       const float* __restrict__ cents,
                       const float* __restrict__ sas) {
    int b = blockIdx.x;
    __shared__ float sv[N_];
    __shared__ int   si[N_];
    int nr = num_rt[b];
    for (int i = threadIdx.x; i < N_; i += blockDim.x) {
        sv[i] = (i < nr) ? attn[b * N_ + i] : -1e9f;
        si[i] = i;
    }
    for (int size = 2; size <= N_; size <<= 1) {
        for (int stride = size >> 1; stride > 0; stride >>= 1) {
            __syncthreads();
            for (int i = threadIdx.x; i < N_; i += blockDim.x) {
                int j = i ^ stride;
                if (j > i) {
                    float vi = sv[i], vj = sv[j];
                    int   ii = si[i], ij = si[j];
                    bool up = ((i & size) == 0);
                    bool jFirst = (vj > vi) || (vj == vi && ij < ii);
                    bool iFirst = (vi > vj) || (vi == vj && ii < ij);
                    bool sw = up ? jFirst : iFirst;
                    if (sw) { sv[i] = vj; sv[j] = vi; si[i] = ij; si[j] = ii; }
                }
            }
        }
    }
    __syncthreads();
    float sh0 = sas[b*4+0], sh1 = sas[b*4+1], sh2 = sas[b*4+2], sc = sas[b*4+3];
    for (int k = threadIdx.x; k < K_; k += blockDim.x) {
        int id = si[k];
        g_top_idx[b][k] = id;
        const float* cp = cents + ((size_t)b * N_ + id) * 3;
        float x = cp[0], y = cp[1], z = cp[2];
        if (id < nr) { x = fmaf(x, sc, sh0); y = fmaf(y, sc, sh1); z = fmaf(z, sc, sh2); }
        g_cent[b][k][0] = x; g_cent[b][k][1] = y; g_cent[b][k][2] = z;
    }
    if (threadIdx.x == 0) g_neff[b] = nr < K_ ? nr : K_;
}

// ---------------- kernel 2: feat = gather(rt) @ W_in + b_in ----------------
// fp32 compute; writes bf16 hi/lo splits (row-major) + per-colblock norm partials.
__global__ void __launch_bounds__(256, 2)
k_feat(const float* __restrict__ rt,
       const float* __restrict__ W_in,
       const float* __restrict__ b_in) {
    int b    = blockIdx.z;
    int row0 = blockIdx.y * 128;
    int col0 = blockIdx.x * 128;
    __shared__ float As[16][128];
    __shared__ float Bs[16][128];
    __shared__ int rows[128];
    int tid = threadIdx.x;
    if (tid < 128) rows[tid] = g_top_idx[b][row0 + tid];
    __syncthreads();
    int tx = tid & 15, ty = tid >> 4;
    int lr = tid >> 1, lq = (tid & 1) * 2;
    int wc = tid >> 4, wq = tid & 15;
    const float* rtb = rt + (size_t)b * N_ * C_;
    size_t arow = (size_t)rows[lr];
    float acc[8][8];
#pragma unroll
    for (int i = 0; i < 8; i++)
#pragma unroll
        for (int j = 0; j < 8; j++) acc[i][j] = 0.f;

    float4 ra[2], rb[2];
#pragma unroll
    for (int i = 0; i < 2; i++) {
        ra[i] = *(const float4*)(rtb + arow * C_ + (lq + i) * 4);
        rb[i] = *(const float4*)(W_in + (size_t)wc * C_ + col0 + i * 64 + wq * 4);
    }
    for (int kk = 0; kk < C_; kk += 16) {
        __syncthreads();
#pragma unroll
        for (int i = 0; i < 2; i++) {
            int q = lq + i;
            As[q*4+0][lr] = ra[i].x; As[q*4+1][lr] = ra[i].y;
            As[q*4+2][lr] = ra[i].z; As[q*4+3][lr] = ra[i].w;
            *(float4*)&Bs[wc][i * 64 + wq * 4] = rb[i];
        }
        __syncthreads();
        if (kk + 16 < C_) {
#pragma unroll
            for (int i = 0; i < 2; i++) {
                ra[i] = *(const float4*)(rtb + arow * C_ + kk + 16 + (lq + i) * 4);
                rb[i] = *(const float4*)(W_in + (size_t)(kk + 16 + wc) * C_ + col0 + i * 64 + wq * 4);
            }
        }
#pragma unroll
        for (int c = 0; c < 16; c++) {
            float a[8], w[8];
            *(float4*)&a[0] = *(const float4*)&As[c][ty * 4];
            *(float4*)&a[4] = *(const float4*)&As[c][64 + ty * 4];
            *(float4*)&w[0] = *(const float4*)&Bs[c][tx * 4];
            *(float4*)&w[4] = *(const float4*)&Bs[c][64 + tx * 4];
#pragma unroll
            for (int i = 0; i < 8; i++)
#pragma unroll
                for (int j = 0; j < 8; j++)
                    acc[i][j] = fmaf(a[i], w[j], acc[i][j]);
        }
    }
    float bias[8];
#pragma unroll
    for (int j = 0; j < 8; j++)
        bias[j] = b_in[col0 + (j < 4 ? tx * 4 + j : 64 + tx * 4 + j - 4)];

    int colA = col0 + tx * 4;
    int colB = col0 + 64 + tx * 4;
#pragma unroll
    for (int i = 0; i < 8; i++) {
        int row = row0 + (i < 4 ? ty * 4 + i : 64 + ty * 4 + i - 4);
        float f[8];
#pragma unroll
        for (int j = 0; j < 8; j++) f[j] = acc[i][j] + bias[j];
        uint32_t hw[4], lw[4];
#pragma unroll
        for (int q2 = 0; q2 < 4; q2++) {
            float v0 = f[q2*2], v1 = f[q2*2+1];
            __nv_bfloat16 h0 = __float2bfloat16_rn(v0);
            __nv_bfloat16 h1 = __float2bfloat16_rn(v1);
            __nv_bfloat16 l0 = __float2bfloat16_rn(v0 - __bfloat162float(h0));
            __nv_bfloat16 l1 = __float2bfloat16_rn(v1 - __bfloat162float(h1));
            hw[q2] = (uint32_t)__bfloat16_as_ushort(h0) | ((uint32_t)__bfloat16_as_ushort(h1) << 16);
            lw[q2] = (uint32_t)__bfloat16_as_ushort(l0) | ((uint32_t)__bfloat16_as_ushort(l1) << 16);
        }
        *(uint2*)&g_fbh[b][row][colA] = make_uint2(hw[0], hw[1]);
        *(uint2*)&g_fbh[b][row][colB] = make_uint2(hw[2], hw[3]);
        *(uint2*)&g_fbl[b][row][colA] = make_uint2(lw[0], lw[1]);
        *(uint2*)&g_fbl[b][row][colB] = make_uint2(lw[2], lw[3]);
        // norm partial over this block's 128 cols (8 per thread, 16 threads share row)
        float s8 = f[0]*f[0] + f[1]*f[1] + f[2]*f[2] + f[3]*f[3]
                 + f[4]*f[4] + f[5]*f[5] + f[6]*f[6] + f[7]*f[7];
#pragma unroll
        for (int off = 1; off < 16; off <<= 1) s8 += __shfl_xor_sync(0xffffffffu, s8, off);
        if (tx == 0) g_fn2p[b][row][blockIdx.x] = s8;
    }
}

// ---------------- kernel 2b: finalize norms ----------------
__global__ void k_fn() {
    int i = blockIdx.x * 256 + threadIdx.x;     // over B_*K_
    const float* pp = &g_fn2p[0][0][0] + (size_t)i * 2;
    float s = pp[0] + pp[1];
    (&g_fn2[0][0])[i] = s;
    (&g_fn [0][0])[i] = sqrtf(s);
}

// ---------------- kernel 3: G tile via mma.sync bf16 3-term + fused argmin ----------------
// SMEM per stage: Ahi,Alo,Bhi,Blo = 4 x 128x64 bf16 (16KB each) = 64KB; 2 stages.
__device__ __forceinline__ void gem_prefetch(const uint4* const* gsrc, uint32_t sb,
                                             int tid, int kc, int stage) {
    uint32_t dbase = sb + stage * 65536;
#pragma unroll
    for (int tl = 0; tl < 4; tl++) {
        const uint4* s = gsrc[tl];
#pragma unroll
        for (int i = 0; i < 4; i++) {
            int idx = tid + i * 256;
            int rr = idx >> 3, uu = idx & 7;
            uint32_t d = dbase + tl * 16384 + (((rr << 3) + (uu ^ (rr & 7))) << 4);
            CP_ASYNC16(d, s + rr * 32 + kc * 8 + uu);
        }
    }
    CP_COMMIT();
}

__global__ void __launch_bounds__(256)
k_gemm(const int* __restrict__ anc,
       const int* __restrict__ pos,
       const int* __restrict__ neg) {
    extern __shared__ __align__(128) unsigned char dsm[];
    int p = blockIdx.z;
    int t = p >> 1, nn = p & 1;
    int ba = anc[t];
    int bb = nn ? neg[t] : pos[t];
    int rtile = blockIdx.y, ctile = blockIdx.x;
    int tid = threadIdx.x, lane = tid & 31, wid = tid >> 5;
    int wr = wid >> 1, wc = wid & 1;
    uint32_t sb = smem_u32(dsm);

    const uint4* gsrc[4];
    gsrc[0] = (const uint4*)&g_fbh[ba][rtile * 128][0];
    gsrc[1] = (const uint4*)&g_fbl[ba][rtile * 128][0];
    gsrc[2] = (const uint4*)&g_fbh[bb][ctile * 128][0];
    gsrc[3] = (const uint4*)&g_fbl[bb][ctile * 128][0];

    float acc[2][8][4];
#pragma unroll
    for (int mb = 0; mb < 2; mb++)
#pragma unroll
        for (int nb = 0; nb < 8; nb++)
#pragma unroll
            for (int c = 0; c < 4; c++) acc[mb][nb][c] = 0.f;

    gem_prefetch(gsrc, sb, tid, 0, 0);

    int mat = lane >> 3, rlo = lane & 7;
    for (int kc = 0; kc < 4; kc++) {
        CP_WAIT0();
        __syncthreads();
        if (kc < 3) gem_prefetch(gsrc, sb, tid, kc + 1, (kc + 1) & 1);
        uint32_t tb = sb + (kc & 1) * 65536;
#pragma unroll
        for (int ks = 0; ks < 4; ks++) {
            int ku = 2 * ks + (mat >> 1);
            uint32_t af[2][2][4];
#pragma unroll
            for (int mb = 0; mb < 2; mb++) {
                int row = wr * 32 + mb * 16 + rlo + ((mat & 1) << 3);
                uint32_t ad = (((row << 3) + (ku ^ (row & 7))) << 4);
                ldsm4(af[mb][0], tb + ad);
                ldsm4(af[mb][1], tb + 16384 + ad);
            }
#pragma unroll
            for (int nbp = 0; nbp < 4; nbp++) {
                int rowb = wc * 64 + nbp * 16 + rlo + ((mat & 1) << 3);
                uint32_t ab = (((rowb << 3) + (ku ^ (rowb & 7))) << 4);
                uint32_t bh[4], bl[4];
                ldsm4(bh, tb + 32768 + ab);
                ldsm4(bl, tb + 49152 + ab);
#pragma unroll
                for (int mb = 0; mb < 2; mb++) {
                    mma16816(acc[mb][nbp*2],   af[mb][0], bh[0], bh[2]);
                    mma16816(acc[mb][nbp*2],   af[mb][0], bl[0], bl[2]);
                    mma16816(acc[mb][nbp*2],   af[mb][1], bh[0], bh[2]);
                    mma16816(acc[mb][nbp*2+1], af[mb][0], bh[1], bh[3]);
                    mma16816(acc[mb][nbp*2+1], af[mb][0], bl[1], bl[3]);
                    mma16816(acc[mb][nbp*2+1], af[mb][1], bh[1], bh[3]);
                }
            }
        }
        __syncthreads();
    }

    // fused partial argmin of fd = fn2[bb][col] - 2G over this CTA's 128 cols
    int t4 = lane >> 2, q = lane & 3;
    float fnc[16];
#pragma unroll
    for (int nb = 0; nb < 8; nb++)
#pragma unroll
        for (int e = 0; e < 2; e++)
            fnc[nb*2+e] = g_fn2[bb][ctile*128 + wc*64 + nb*8 + q*2 + e];
#pragma unroll
    for (int mb = 0; mb < 2; mb++) {
#pragma unroll
        for (int half = 0; half < 2; half++) {
            int row = rtile*128 + wr*32 + mb*16 + t4 + half*8;
            float bv = 3.4e38f; int bi = 0x7fffffff;
#pragma unroll
            for (int nb = 0; nb < 8; nb++) {
#pragma unroll
                for (int e = 0; e < 2; e++) {
                    float fd = fnc[nb*2+e] - 2.f * acc[mb][nb][half*2+e];
                    int col = ctile*128 + wc*64 + nb*8 + q*2 + e;
                    if (fd < bv) { bv = fd; bi = col; }
                }
            }
#pragma unroll
            for (int off = 1; off < 4; off <<= 1) {
                float ov = __shfl_xor_sync(0xffffffffu, bv, off);
                int   oi = __shfl_xor_sync(0xffffffffu, bi, off);
                if (ov < bv || (ov == bv && oi < bi)) { bv = ov; bi = oi; }
            }
            if (q == 0) {
                g_pmv[p][row][ctile*2 + wc] = bv;
                g_pmi[p][row][ctile*2 + wc] = bi;
            }
        }
    }
}

// ---------------- kernel 4: reduce partials -> corr, s, q_c ----------------
__global__ void k_corr_red(const int* __restrict__ anc,
                           const int* __restrict__ pos,
                           const int* __restrict__ neg) {
    int p = blockIdx.x;
    int k = threadIdx.x;
    int t = p >> 1, n = p & 1;
    int ba = anc[t];
    int bb = n ? neg[t] : pos[t];
    float bv = 3.4e38f; int bi = 0x7fffffff;
#pragma unroll
    for (int j = 0; j < 8; j++) {
        float v = g_pmv[p][k][j];
        int   i = g_pmi[p][k][j];
        if (v < bv || (v == bv && i < bi)) { bv = v; bi = i; }
    }
    float dot  = 0.5f * (g_fn2[bb][bi] - bv);
    float cosv = dot / (g_fn[ba][k] * g_fn[bb][bi] + 1e-8f);
    g_s[p][k] = cosv > 0.f ? cosv : 0.f;
    g_qc[p][k][0] = g_cent[bb][bi][0];
    g_qc[p][k][1] = g_cent[bb][bi][1];
    g_qc[p][k][2] = g_cent[bb][bi][2];
}

// ---------------- kernel 5: build geo bitmask ----------------
__global__ void k_buildM(const int* __restrict__ anc,
                         const int* __restrict__ pos,
                         const int* __restrict__ neg) {
    int p = blockIdx.x;
    int t = p >> 1, n = p & 1;
    int ba = anc[t];
    int bb = n ? neg[t] : pos[t];
    __shared__ float px[K_], py[K_], pz[K_], pn[K_];
    __shared__ float qx[K_], qy[K_], qz[K_], qn[K_];
    int tid = threadIdx.x;
    {
        float x = g_cent[ba][tid][0], y = g_cent[ba][tid][1], z = g_cent[ba][tid][2];
        px[tid] = x; py[tid] = y; pz[tid] = z; pn[tid] = x*x + y*y + z*z;
        x = g_qc[p][tid][0]; y = g_qc[p][tid][1]; z = g_qc[p][tid][2];
        qx[tid] = x; qy[tid] = y; qz[tid] = z; qn[tid] = x*x + y*y + z*z;
    }
    __syncthreads();
    int neffa = g_neff[ba], neffb = g_neff[bb];
    int warp = tid >> 5, lane = tid & 31;
    for (int k = warp; k < K_; k += 16) {
        float pxk = px[k], pyk = py[k], pzk = pz[k], pnk = pn[k];
        float qxk = qx[k], qyk = qy[k], qzk = qz[k], qnk = qn[k];
        bool kv = (k < neffa);
#pragma unroll 4
        for (int w = 0; w < 16; w++) {
            int l = w * 32 + lane;
            float dp2 = fmaxf(pnk + pn[l] - 2.f*(pxk*px[l] + pyk*py[l] + pzk*pz[l]), 0.f) + 1e-12f;
            float dq2 = fmaxf(qnk + qn[l] - 2.f*(qxk*qx[l] + qyk*qy[l] + qzk*qz[l]), 0.f) + 1e-12f;
            float u = dp2 + dq2 - 0.25f;
            bool geo = (u < 0.f) || (4.f * dp2 * dq2 > u * u);
            bool ok = geo && kv && (l < neffb) && (l != k);
            unsigned word = __ballot_sync(0xffffffffu, ok);
            if (lane == 0) g_mask[p][k][w] = word;
        }
    }
}

// ---------------- kernel 6: masked power iteration + sort + MLP ----------------
__global__ void k_power(const float* __restrict__ W1, const float* __restrict__ b1,
                        const float* __restrict__ W2, const float* __restrict__ b2,
                        float* __restrict__ out) {
    int p = blockIdx.x;
    int tid = threadIdx.x;
    int warp = tid >> 5, lane = tid & 31;
    __shared__ unsigned msk[K_][16];
    __shared__ float v[K_], w[K_], u[K_], s_sm[K_];
    __shared__ float red[16];
    {
        const uint4* gm = (const uint4*)&g_mask[p][0][0];
        uint4* sm = (uint4*)&msk[0][0];
        for (int i = tid; i < K_ * 4; i += 512) sm[i] = gm[i];
    }
    s_sm[tid] = g_s[p][tid];
    v[tid] = 0.044194173824159216f;
    __syncthreads();
    for (int it = 0; it < 20; it++) {
        u[tid] = s_sm[tid] * v[tid];
        __syncthreads();
        float ur[16];
#pragma unroll
        for (int c = 0; c < 16; c++) ur[c] = u[c * 32 + lane];
        for (int k = warp; k < K_; k += 16) {
            const uint4* m4 = (const uint4*)msk[k];
            float acc = 0.f;
#pragma unroll
            for (int c4 = 0; c4 < 4; c4++) {
                uint4 mw = m4[c4];
                if ((mw.x >> lane) & 1u) acc += ur[c4 * 4 + 0];
                if ((mw.y >> lane) & 1u) acc += ur[c4 * 4 + 1];
                if ((mw.z >> lane) & 1u) acc += ur[c4 * 4 + 2];
                if ((mw.w >> lane) & 1u) acc += ur[c4 * 4 + 3];
            }
#pragma unroll
            for (int o = 16; o; o >>= 1) acc += __shfl_xor_sync(0xffffffffu, acc, o);
            if (lane == 0) w[k] = acc * s_sm[k];
        }
        __syncthreads();
        float x = w[tid];
        float sq = x * x;
#pragma unroll
        for (int o = 16; o; o >>= 1) sq += __shfl_xor_sync(0xffffffffu, sq, o);
        if (lane == 0) red[warp] = sq;
        __syncthreads();
        if (warp == 0) {
            float r = (lane < 16) ? red[lane] : 0.f;
#pragma unroll
            for (int o = 8; o; o >>= 1) r += __shfl_xor_sync(0xffffffffu, r, o);
            if (lane == 0) red[0] = 1.f / (sqrtf(r) + 1e-8f);
        }
        __syncthreads();
        v[tid] = x * red[0];
        __syncthreads();
    }
    for (int size = 2; size <= K_; size <<= 1) {
        for (int stride = size >> 1; stride > 0; stride >>= 1) {
            int i = tid, j = i ^ stride;
            if (j > i) {
                float vi = v[i], vj = v[j];
                bool up = ((i & size) == 0);
                bool sw = up ? (vj > vi) : (vi > vj);
                if (sw) { v[i] = vj; v[j] = vi; }
            }
            __syncthreads();
        }
    }
    float hj = b1[tid];
#pragma unroll 4
    for (int k = 0; k < K_; k++)
        hj = fmaf(v[k], W1[(size_t)k * K_ + tid], hj);
    hj = hj > 0.f ? hj : 0.f;
    float contrib = hj * W2[tid];
#pragma unroll
    for (int o = 16; o; o >>= 1) contrib += __shfl_xor_sync(0xffffffffu, contrib, o);
    if (lane == 0) red[warp] = contrib;
    __syncthreads();
    if (tid == 0) {
        float sum = 0.f;
#pragma unroll
        for (int i = 0; i < 16; i++) sum += red[i];
        sum += b2[0];
        out[p]       = 1.f / (1.f + expf(-sum));
        out[NP_ + p] = (p & 1) ? 0.f : 1.f;
    }
}

extern "C" void kernel_launch(void* const* d_in, const int* in_sizes, int n_in,
                              void* d_out, int out_size) {
    const float* rt     = (const float*)d_in[0];
    const float* cents  = (const float*)d_in[1];
    const float* attn   = (const float*)d_in[2];
    const float* sas    = (const float*)d_in[3];
    const int*   num_rt = (const int*)  d_in[4];
    const int*   anc    = (const int*)  d_in[5];
    const int*   pos    = (const int*)  d_in[6];
    const int*   neg    = (const int*)  d_in[7];
    const float* W_in   = (const float*)d_in[8];
    const float* b_in   = (const float*)d_in[9];
    const float* W1     = (const float*)d_in[10];
    const float* b1     = (const float*)d_in[11];
    const float* W2     = (const float*)d_in[12];
    const float* b2     = (const float*)d_in[13];
    float* out = (float*)d_out;

    cudaFuncSetAttribute(k_gemm, cudaFuncAttributeMaxDynamicSharedMemorySize, 131072);

    k_topk    <<<B_, 512>>>(attn, num_rt, cents, sas);
    k_feat    <<<dim3(C_/128, K_/128, B_), 256>>>(rt, W_in, b_in);
    k_fn      <<<B_*K_/256, 256>>>();
    k_gemm    <<<dim3(4, 4, NP_), 256, 131072>>>(anc, pos, neg);
    k_corr_red<<<NP_, 512>>>(anc, pos, neg);
    k_buildM  <<<NP_, 512>>>(anc, pos, neg);
    k_power   <<<NP_, 512>>>(W1, b1, W2, b2, out);
}

// round 5
// speedup vs baseline: 4.1777x; 1.0654x over previous
#include <cuda_runtime.h>
#include <cuda_bf16.h>
#include <math.h>
#include <stdint.h>

#define B_ 64
#define N_ 1024
#define C_ 256
#define K_ 512
#define T_ 64
#define NP_ 128   // T*2 pairs

// ---------------- static device scratch ----------------
static __device__ int      g_top_idx[B_][K_];
static __device__ int      g_neff[B_];
static __device__ float    g_cent[B_][K_][3];
static __device__ __align__(16) __nv_bfloat16 g_rh[B_][K_][C_];   // gathered rt hi
static __device__ __align__(16) __nv_bfloat16 g_rl[B_][K_][C_];   // gathered rt lo
static __device__ __align__(16) __nv_bfloat16 g_wh[C_][C_];       // W_in^T hi [n][k]
static __device__ __align__(16) __nv_bfloat16 g_wl[C_][C_];       // W_in^T lo
static __device__ __align__(16) __nv_bfloat16 g_fbh[B_][K_][C_];  // feat hi
static __device__ __align__(16) __nv_bfloat16 g_fbl[B_][K_][C_];  // feat lo
static __device__ float    g_fn2p[B_][K_][4];
static __device__ float    g_fn2[B_][K_];
static __device__ float    g_fn [B_][K_];
static __device__ float    g_pmv[NP_][K_][8];
static __device__ int      g_pmi[NP_][K_][8];

// ---------------- asm helpers ----------------
__device__ __forceinline__ uint32_t smem_u32(const void* p) {
    uint32_t a;
    asm("{ .reg .u64 t; cvta.to.shared.u64 t, %1; cvt.u32.u64 %0, t; }" : "=r"(a) : "l"(p));
    return a;
}
__device__ __forceinline__ void ldsm4(uint32_t* r, uint32_t a) {
    asm volatile("ldmatrix.sync.aligned.m8n8.x4.shared.b16 {%0,%1,%2,%3}, [%4];"
        : "=r"(r[0]), "=r"(r[1]), "=r"(r[2]), "=r"(r[3]) : "r"(a));
}
__device__ __forceinline__ void mma16816(float* c, const uint32_t* a, uint32_t b0, uint32_t b1) {
    asm volatile("mma.sync.aligned.m16n8k16.row.col.f32.bf16.bf16.f32 "
        "{%0,%1,%2,%3}, {%4,%5,%6,%7}, {%8,%9}, {%0,%1,%2,%3};"
        : "+f"(c[0]), "+f"(c[1]), "+f"(c[2]), "+f"(c[3])
        : "r"(a[0]), "r"(a[1]), "r"(a[2]), "r"(a[3]), "r"(b0), "r"(b1));
}
#define CP_ASYNC16(dst, src) asm volatile("cp.async.cg.shared.global [%0], [%1], 16;" :: "r"(dst), "l"(src))
#define CP_COMMIT()          asm volatile("cp.async.commit_group;" ::: "memory")
#define CP_WAIT0()           asm volatile("cp.async.wait_group 0;" ::: "memory")

__device__ __forceinline__ uint32_t split_pack_hi(float v0, float v1, uint32_t& lo) {
    __nv_bfloat16 h0 = __float2bfloat16_rn(v0);
    __nv_bfloat16 h1 = __float2bfloat16_rn(v1);
    __nv_bfloat16 l0 = __float2bfloat16_rn(v0 - __bfloat162float(h0));
    __nv_bfloat16 l1 = __float2bfloat16_rn(v1 - __bfloat162float(h1));
    lo = (uint32_t)__bfloat16_as_ushort(l0) | ((uint32_t)__bfloat16_as_ushort(l1) << 16);
    return (uint32_t)__bfloat16_as_ushort(h0) | ((uint32_t)__bfloat16_as_ushort(h1) << 16);
}

// ---------------- kernel 1: masked top-K via bitonic sort ----------------
__global__ void k_topk(const float* __restrict__ attn,
                       const int*   __restrict__ num_rt,
                       const float* __restrict__ cents,
                       const float* __restrict__ sas) {
    int b = blockIdx.x;
    __shared__ float sv[N_];
    __shared__ int   si[N_];
    int nr = num_rt[b];
    for (int i = threadIdx.x; i < N_; i += blockDim.x) {
        sv[i] = (i < nr) ? attn[b * N_ + i] : -1e9f;
        si[i] = i;
    }
    for (int size = 2; size <= N_; size <<= 1) {
        for (int stride = size >> 1; stride > 0; stride >>= 1) {
            __syncthreads();
            for (int i = threadIdx.x; i < N_; i += blockDim.x) {
                int j = i ^ stride;
                if (j > i) {
                    float vi = sv[i], vj = sv[j];
                    int   ii = si[i], ij = si[j];
                    bool up = ((i & size) == 0);
                    bool jFirst = (vj > vi) || (vj == vi && ij < ii);
                    bool iFirst = (vi > vj) || (vi == vj && ii < ij);
                    bool sw = up ? jFirst : iFirst;
                    if (sw) { sv[i] = vj; sv[j] = vi; si[i] = ij; si[j] = ii; }
                }
            }
        }
    }
    __syncthreads();
    float sh0 = sas[b*4+0], sh1 = sas[b*4+1], sh2 = sas[b*4+2], sc = sas[b*4+3];
    for (int k = threadIdx.x; k < K_; k += blockDim.x) {
        int id = si[k];
        g_top_idx[b][k] = id;
        const float* cp = cents + ((size_t)b * N_ + id) * 3;
        float x = cp[0], y = cp[1], z = cp[2];
        if (id < nr) { x = fmaf(x, sc, sh0); y = fmaf(y, sc, sh1); z = fmaf(z, sc, sh2); }
        g_cent[b][k][0] = x; g_cent[b][k][1] = y; g_cent[b][k][2] = z;
    }
    if (threadIdx.x == 0) g_neff[b] = nr < K_ ? nr : K_;
}

// ---------------- prep: W_in^T bf16 hi/lo ----------------
__global__ void k_wt(const float* __restrict__ W_in) {
    int k = blockIdx.x, n = threadIdx.x;
    float v = W_in[k * C_ + n];
    __nv_bfloat16 h = __float2bfloat16_rn(v);
    __nv_bfloat16 l = __float2bfloat16_rn(v - __bfloat162float(h));
    g_wh[n][k] = h;
    g_wl[n][k] = l;
}

// ---------------- prep: gather top-K rt rows to bf16 hi/lo ----------------
__global__ void k_gather(const float* __restrict__ rt) {
    int idx  = blockIdx.x * 8 + (threadIdx.x >> 5);  // global row in [0, B*K)
    int lane = threadIdx.x & 31;
    int b = idx >> 9, k = idx & (K_ - 1);
    int src = g_top_idx[b][k];
    const float4* r = (const float4*)(rt + ((size_t)b * N_ + src) * C_);
    float4 u = r[lane * 2], w2 = r[lane * 2 + 1];
    float f[8] = {u.x, u.y, u.z, u.w, w2.x, w2.y, w2.z, w2.w};
    uint32_t hw[4], lw[4];
#pragma unroll
    for (int q = 0; q < 4; q++) hw[q] = split_pack_hi(f[q*2], f[q*2+1], lw[q]);
    *(uint4*)&g_rh[b][k][lane * 8] = make_uint4(hw[0], hw[1], hw[2], hw[3]);
    *(uint4*)&g_rl[b][k][lane * 8] = make_uint4(lw[0], lw[1], lw[2], lw[3]);
}

// ---------------- shared GEMM plumbing (128x128 tile, K-chunk 64, 2 stages) ----------------
__device__ __forceinline__ void gem_prefetch(const uint4* const* gsrc, uint32_t sb,
                                             int tid, int kc, int stage) {
    uint32_t dbase = sb + stage * 65536;
#pragma unroll
    for (int tl = 0; tl < 4; tl++) {
        const uint4* s = gsrc[tl];
#pragma unroll
        for (int i = 0; i < 4; i++) {
            int idx = tid + i * 256;
            int rr = idx >> 3, uu = idx & 7;
            uint32_t d = dbase + tl * 16384 + (((rr << 3) + (uu ^ (rr & 7))) << 4);
            CP_ASYNC16(d, s + rr * 32 + kc * 8 + uu);
        }
    }
    CP_COMMIT();
}

// mainloop: 3-term bf16 MMA over 4 K-chunks; acc[2][8][4] per thread
__device__ __forceinline__ void gem_mainloop(const uint4* const* gsrc, uint32_t sb,
                                             int tid, float acc[2][8][4]) {
    int lane = tid & 31, wid = tid >> 5;
    int wr = wid >> 1, wc = wid & 1;
    int mat = lane >> 3, rlo = lane & 7;
    gem_prefetch(gsrc, sb, tid, 0, 0);
    for (int kc = 0; kc < 4; kc++) {
        CP_WAIT0();
        __syncthreads();
        if (kc < 3) gem_prefetch(gsrc, sb, tid, kc + 1, (kc + 1) & 1);
        uint32_t tb = sb + (kc & 1) * 65536;
#pragma unroll
        for (int ks = 0; ks < 4; ks++) {
            int ku = 2 * ks + (mat >> 1);
            uint32_t af[2][2][4];
#pragma unroll
            for (int mb = 0; mb < 2; mb++) {
                int row = wr * 32 + mb * 16 + rlo + ((mat & 1) << 3);
                uint32_t ad = (((row << 3) + (ku ^ (row & 7))) << 4);
                ldsm4(af[mb][0], tb + ad);
                ldsm4(af[mb][1], tb + 16384 + ad);
            }
#pragma unroll
            for (int nbp = 0; nbp < 4; nbp++) {
                int rowb = wc * 64 + nbp * 16 + rlo + ((mat & 1) << 3);
                uint32_t ab = (((rowb << 3) + (ku ^ (rowb & 7))) << 4);
                uint32_t bh[4], bl[4];
                ldsm4(bh, tb + 32768 + ab);
                ldsm4(bl, tb + 49152 + ab);
#pragma unroll
                for (int mb = 0; mb < 2; mb++) {
                    mma16816(acc[mb][nbp*2],   af[mb][0], bh[0], bh[2]);
                    mma16816(acc[mb][nbp*2],   af[mb][0], bl[0], bl[2]);
                    mma16816(acc[mb][nbp*2],   af[mb][1], bh[0], bh[2]);
                    mma16816(acc[mb][nbp*2+1], af[mb][0], bh[1], bh[3]);
                    mma16816(acc[mb][nbp*2+1], af[mb][0], bl[1], bl[3]);
                    mma16816(acc[mb][nbp*2+1], af[mb][1], bh[1], bh[3]);
                }
            }
        }
        __syncthreads();
    }
}

// ---------------- kernel 2: feat = gather(rt) @ W_in + b_in via MMA ----------------
__global__ void __launch_bounds__(256)
k_featmma(const float* __restrict__ b_in) {
    extern __shared__ __align__(128) unsigned char dsm[];
    int b     = blockIdx.z;
    int rtile = blockIdx.y;
    int ctile = blockIdx.x;          // n half: 0 or 1
    int tid = threadIdx.x, lane = tid & 31, wid = tid >> 5;
    int wr = wid >> 1, wc = wid & 1;
    uint32_t sb = smem_u32(dsm);

    const uint4* gsrc[4];
    gsrc[0] = (const uint4*)&g_rh[b][rtile * 128][0];
    gsrc[1] = (const uint4*)&g_rl[b][rtile * 128][0];
    gsrc[2] = (const uint4*)&g_wh[ctile * 128][0];
    gsrc[3] = (const uint4*)&g_wl[ctile * 128][0];

    float acc[2][8][4];
#pragma unroll
    for (int mb = 0; mb < 2; mb++)
#pragma unroll
        for (int nb = 0; nb < 8; nb++)
#pragma unroll
            for (int c = 0; c < 4; c++) acc[mb][nb][c] = 0.f;

    gem_mainloop(gsrc, sb, tid, acc);

    int t4 = lane >> 2, q = lane & 3;
#pragma unroll
    for (int mb = 0; mb < 2; mb++) {
#pragma unroll
        for (int half = 0; half < 2; half++) {
            int row = rtile * 128 + wr * 32 + mb * 16 + t4 + half * 8;
            float s8 = 0.f;
#pragma unroll
            for (int nb = 0; nb < 8; nb++) {
                int col = ctile * 128 + wc * 64 + nb * 8 + q * 2;
                float f0 = acc[mb][nb][half*2+0] + b_in[col];
                float f1 = acc[mb][nb][half*2+1] + b_in[col + 1];
                uint32_t lw;
                uint32_t hw = split_pack_hi(f0, f1, lw);
                *(uint32_t*)&g_fbh[b][row][col] = hw;
                *(uint32_t*)&g_fbl[b][row][col] = lw;
                s8 += f0 * f0 + f1 * f1;
            }
            s8 += __shfl_xor_sync(0xffffffffu, s8, 1);
            s8 += __shfl_xor_sync(0xffffffffu, s8, 2);
            if (q == 0) g_fn2p[b][row][ctile * 2 + wc] = s8;
        }
    }
}

// ---------------- kernel 2b: finalize norms ----------------
__global__ void k_fn() {
    int i = blockIdx.x * 256 + threadIdx.x;
    const float* pp = &g_fn2p[0][0][0] + (size_t)i * 4;
    float s = (pp[0] + pp[1]) + (pp[2] + pp[3]);
    (&g_fn2[0][0])[i] = s;
    (&g_fn [0][0])[i] = sqrtf(s);
}

// ---------------- kernel 3: G tile + fused partial argmin ----------------
__global__ void __launch_bounds__(256)
k_gemm(const int* __restrict__ anc,
       const int* __restrict__ pos,
       const int* __restrict__ neg) {
    extern __shared__ __align__(128) unsigned char dsm[];
    int p = blockIdx.z;
    int t = p >> 1, nn = p & 1;
    int ba = anc[t];
    int bb = nn ? neg[t] : pos[t];
    int rtile = blockIdx.y, ctile = blockIdx.x;
    int tid = threadIdx.x, lane = tid & 31, wid = tid >> 5;
    int wr = wid >> 1, wc = wid & 1;
    uint32_t sb = smem_u32(dsm);

    const uint4* gsrc[4];
    gsrc[0] = (const uint4*)&g_fbh[ba][rtile * 128][0];
    gsrc[1] = (const uint4*)&g_fbl[ba][rtile * 128][0];
    gsrc[2] = (const uint4*)&g_fbh[bb][ctile * 128][0];
    gsrc[3] = (const uint4*)&g_fbl[bb][ctile * 128][0];

    float acc[2][8][4];
#pragma unroll
    for (int mb = 0; mb < 2; mb++)
#pragma unroll
        for (int nb = 0; nb < 8; nb++)
#pragma unroll
            for (int c = 0; c < 4; c++) acc[mb][nb][c] = 0.f;

    gem_mainloop(gsrc, sb, tid, acc);

    int t4 = lane >> 2, q = lane & 3;
    float fnc[16];
#pragma unroll
    for (int nb = 0; nb < 8; nb++)
#pragma unroll
        for (int e = 0; e < 2; e++)
            fnc[nb*2+e] = g_fn2[bb][ctile*128 + wc*64 + nb*8 + q*2 + e];
#pragma unroll
    for (int mb = 0; mb < 2; mb++) {
#pragma unroll
        for (int half = 0; half < 2; half++) {
            int row = rtile*128 + wr*32 + mb*16 + t4 + half*8;
            float bv = 3.4e38f; int bi = 0x7fffffff;
#pragma unroll
            for (int nb = 0; nb < 8; nb++) {
#pragma unroll
                for (int e = 0; e < 2; e++) {
                    float fd = fnc[nb*2+e] - 2.f * acc[mb][nb][half*2+e];
                    int col = ctile*128 + wc*64 + nb*8 + q*2 + e;
                    if (fd < bv) { bv = fd; bi = col; }
                }
            }
#pragma unroll
            for (int off = 1; off < 4; off <<= 1) {
                float ov = __shfl_xor_sync(0xffffffffu, bv, off);
                int   oi = __shfl_xor_sync(0xffffffffu, bi, off);
                if (ov < bv || (ov == bv && oi < bi)) { bv = ov; bi = oi; }
            }
            if (q == 0) {
                g_pmv[p][row][ctile*2 + wc] = bv;
                g_pmi[p][row][ctile*2 + wc] = bi;
            }
        }
    }
}

// ---------------- kernel 4: fused tail (corr reduce + mask + power + MLP) ----------------
__global__ void __launch_bounds__(512)
k_tail(const int* __restrict__ anc, const int* __restrict__ pos,
       const int* __restrict__ neg,
       const float* __restrict__ W1, const float* __restrict__ b1,
       const float* __restrict__ W2, const float* __restrict__ b2,
       float* __restrict__ out) {
    extern __shared__ __align__(16) unsigned char dsm[];
    unsigned (*msk)[16] = (unsigned(*)[16])dsm;              // 32 KB
    float* px   = (float*)(dsm + 32768);
    float* py   = px + K_;
    float* pz   = py + K_;
    float* pn   = pz + K_;
    float* qx   = pn + K_;
    float* qy   = qx + K_;
    float* qz   = qy + K_;
    float* qn   = qz + K_;                                   // +16 KB
    float* s_sm = qn + K_;                                   // 2 KB
    float* v    = s_sm + K_;
    float* w    = v + K_;
    float* u    = w + K_;
    float* red  = u + K_;                                    // 16 floats

    int p = blockIdx.x;
    int tid = threadIdx.x;
    int warp = tid >> 5, lane = tid & 31;
    int t = p >> 1, n = p & 1;
    int ba = anc[t];
    int bb = n ? neg[t] : pos[t];

    // ---- stage 1: reduce argmin partials -> s, q_c ----
    {
        int k = tid;
        float bv = 3.4e38f; int bi = 0x7fffffff;
#pragma unroll
        for (int j = 0; j < 8; j++) {
            float pv = g_pmv[p][k][j];
            int   pi = g_pmi[p][k][j];
            if (pv < bv || (pv == bv && pi < bi)) { bv = pv; bi = pi; }
        }
        float fn2b = g_fn2[bb][bi];
        float dot  = 0.5f * (fn2b - bv);
        float cosv = dot / (g_fn[ba][k] * g_fn[bb][bi] + 1e-8f);
        s_sm[k] = cosv > 0.f ? cosv : 0.f;
        float x = g_cent[ba][k][0], y = g_cent[ba][k][1], z = g_cent[ba][k][2];
        px[k] = x; py[k] = y; pz[k] = z; pn[k] = x*x + y*y + z*z;
        x = g_cent[bb][bi][0]; y = g_cent[bb][bi][1]; z = g_cent[bb][bi][2];
        qx[k] = x; qy[k] = y; qz[k] = z; qn[k] = x*x + y*y + z*z;
    }
    __syncthreads();

    // ---- stage 2: geo mask via ballot, into SMEM ----
    {
        int neffa = g_neff[ba], neffb = g_neff[bb];
        for (int k = warp; k < K_; k += 16) {
            float pxk = px[k], pyk = py[k], pzk = pz[k], pnk = pn[k];
            float qxk = qx[k], qyk = qy[k], qzk = qz[k], qnk = qn[k];
            bool kv = (k < neffa);
#pragma unroll 4
            for (int ww = 0; ww < 16; ww++) {
                int l = ww * 32 + lane;
                float dp2 = fmaxf(pnk + pn[l] - 2.f*(pxk*px[l] + pyk*py[l] + pzk*pz[l]), 0.f) + 1e-12f;
                float dq2 = fmaxf(qnk + qn[l] - 2.f*(qxk*qx[l] + qyk*qy[l] + qzk*qz[l]), 0.f) + 1e-12f;
                float uu = dp2 + dq2 - 0.25f;
                bool geo = (uu < 0.f) || (4.f * dp2 * dq2 > uu * uu);
                bool ok = geo && kv && (l < neffb) && (l != k);
                unsigned word = __ballot_sync(0xffffffffu, ok);
                if (lane == 0) msk[k][ww] = word;
            }
        }
    }
    v[tid] = 0.044194173824159216f;   // 1/sqrt(512)
    __syncthreads();

    // ---- stage 3: power iteration ----
    for (int it = 0; it < 20; it++) {
        u[tid] = s_sm[tid] * v[tid];
        __syncthreads();
        float ur[16];
#pragma unroll
        for (int c = 0; c < 16; c++) ur[c] = u[c * 32 + lane];
        for (int k = warp; k < K_; k += 16) {
            const uint4* m4 = (const uint4*)msk[k];
            float acc = 0.f;
#pragma unroll
            for (int c4 = 0; c4 < 4; c4++) {
                uint4 mw = m4[c4];
                if ((mw.x >> lane) & 1u) acc += ur[c4 * 4 + 0];
                if ((mw.y >> lane) & 1u) acc += ur[c4 * 4 + 1];
                if ((mw.z >> lane) & 1u) acc += ur[c4 * 4 + 2];
                if ((mw.w >> lane) & 1u) acc += ur[c4 * 4 + 3];
            }
#pragma unroll
            for (int o = 16; o; o >>= 1) acc += __shfl_xor_sync(0xffffffffu, acc, o);
            if (lane == 0) w[k] = acc * s_sm[k];
        }
        __syncthreads();
        float x = w[tid];
        float sq = x * x;
#pragma unroll
        for (int o = 16; o; o >>= 1) sq += __shfl_xor_sync(0xffffffffu, sq, o);
        if (lane == 0) red[warp] = sq;
        __syncthreads();
        if (warp == 0) {
            float r = (lane < 16) ? red[lane] : 0.f;
#pragma unroll
            for (int o = 8; o; o >>= 1) r += __shfl_xor_sync(0xffffffffu, r, o);
            if (lane == 0) red[0] = 1.f / (sqrtf(r) + 1e-8f);
        }
        __syncthreads();
        v[tid] = x * red[0];
        __syncthreads();
    }
    // ---- sort descending ----
    for (int size = 2; size <= K_; size <<= 1) {
        for (int stride = size >> 1; stride > 0; stride >>= 1) {
            int i = tid, j = i ^ stride;
            if (j > i) {
                float vi = v[i], vj = v[j];
                bool up = ((i & size) == 0);
                bool sw = up ? (vj > vi) : (vi > vj);
                if (sw) { v[i] = vj; v[j] = vi; }
            }
            __syncthreads();
        }
    }
    // ---- MLP ----
    float hj = b1[tid];
#pragma unroll 4
    for (int k = 0; k < K_; k++)
        hj = fmaf(v[k], W1[(size_t)k * K_ + tid], hj);
    hj = hj > 0.f ? hj : 0.f;
    float contrib = hj * W2[tid];
#pragma unroll
    for (int o = 16; o; o >>= 1) contrib += __shfl_xor_sync(0xffffffffu, contrib, o);
    if (lane == 0) red[warp] = contrib;
    __syncthreads();
    if (tid == 0) {
        float sum = 0.f;
#pragma unroll
        for (int i = 0; i < 16; i++) sum += red[i];
        sum += b2[0];
        out[p]       = 1.f / (1.f + expf(-sum));
        out[NP_ + p] = (p & 1) ? 0.f : 1.f;
    }
}

extern "C" void kernel_launch(void* const* d_in, const int* in_sizes, int n_in,
                              void* d_out, int out_size) {
    const float* rt     = (const float*)d_in[0];
    const float* cents  = (const float*)d_in[1];
    const float* attn   = (const float*)d_in[2];
    const float* sas    = (const float*)d_in[3];
    const int*   num_rt = (const int*)  d_in[4];
    const int*   anc    = (const int*)  d_in[5];
    const int*   pos    = (const int*)  d_in[6];
    const int*   neg    = (const int*)  d_in[7];
    const float* W_in   = (const float*)d_in[8];
    const float* b_in   = (const float*)d_in[9];
    const float* W1     = (const float*)d_in[10];
    const float* b1     = (const float*)d_in[11];
    const float* W2     = (const float*)d_in[12];
    const float* b2     = (const float*)d_in[13];
    float* out = (float*)d_out;

    static int s_init = 0;
    if (!s_init) {
        cudaFuncSetAttribute(k_featmma, cudaFuncAttributeMaxDynamicSharedMemorySize, 131072);
        cudaFuncSetAttribute(k_gemm,    cudaFuncAttributeMaxDynamicSharedMemorySize, 131072);
        cudaFuncSetAttribute(k_tail,    cudaFuncAttributeMaxDynamicSharedMemorySize, 57472);
        s_init = 1;
    }

    k_topk   <<<B_, 512>>>(attn, num_rt, cents, sas);
    k_wt     <<<C_, C_>>>(W_in);
    k_gather <<<B_*K_/8, 256>>>(rt);
    k_featmma<<<dim3(2, 4, B_), 256, 131072>>>(b_in);
    k_fn     <<<B_*K_/256, 256>>>();
    k_gemm   <<<dim3(4, 4, NP_), 256, 131072>>>(anc, pos, neg);
    k_tail   <<<NP_, 512, 57472>>>(anc, pos, neg, W1, b1, W2, b2, out);
}